// round 8
// baseline (speedup 1.0000x reference)
#include <cuda_runtime.h>
#include <cstdint>

#define RADIUS   4
#define MAX_DISP 192
#define BATCH    2
#define H        256
#define W        512
#define HC       248           // H - 8
#define WC       504           // W - 8
#define BH       4             // output rows per block
#define ROWBLKS  (HC / BH)     // 62
#define NBLOCKS  (ROWBLKS * BATCH)  // 124 -> one wave on 148 SMs
#define TILE_H   (BH + 2 * RADIUS)  // 12
#define NTHREADS 1024
#define NQUADS   (BH * (WC / 4))    // 504 quads per block

// integer-exact accumulators; module-load init = 0, last block resets after use
__device__ unsigned int g_acc[2] = {0u, 0u};
__device__ unsigned int g_done = 0u;

extern __shared__ float smem_raw[];
// layout: lt[12*512] | rt[12*512] | sc0[4*504] | sc1[4*504] | sc2[4*504]  (u32)

// Census bit via float-subtract sign: predicate-free, 3 fixed-lat ops
//   d = c - v  (FADD, fma pipe);  s = sign-extend(d) (SHF, alu);
//   acc = acc + acc - s  (IADD3, alu).
// Exact: inputs are non-negative; sign(fl(c-v)) == sign(c-v), ties -> +0 -> bit 0.
__device__ __forceinline__ void census_bit(unsigned& acc, float v, float c) {
    const float d = c - v;                       // < 0  iff  v > c
    const int   s = __float_as_int(d) >> 31;     // -1 if v > c else 0
    acc = acc + acc - (unsigned)s;               // acc = 2*acc + bit
}

// Census for 4 consecutive pixels (row rr, cols wx..wx+3) from a 12x512 smem tile.
// Bits packed MSB-first; bit order identical for left/right (popc(XOR) invariant).
__device__ __forceinline__ void census4(const float* __restrict__ t, int rr, int wx,
                                        unsigned a[4][3]) {
    const float4 cv = *(const float4*)&t[(rr + 4) * W + wx + 4];
    const float c[4] = {cv.x, cv.y, cv.z, cv.w};
    #pragma unroll
    for (int p = 0; p < 4; p++) { a[p][0] = 0u; a[p][1] = 0u; a[p][2] = 0u; }
    int k = 0;
    #pragma unroll
    for (int i = 0; i < 9; i++) {
        const float4 v0 = *(const float4*)&t[(rr + i) * W + wx];
        const float4 v1 = *(const float4*)&t[(rr + i) * W + wx + 4];
        const float4 v2 = *(const float4*)&t[(rr + i) * W + wx + 8];
        const float v[12] = {v0.x, v0.y, v0.z, v0.w,
                             v1.x, v1.y, v1.z, v1.w,
                             v2.x, v2.y, v2.z, v2.w};
        #pragma unroll
        for (int j = 0; j < 9; j++) {
            if (i == 4 && j == 4) continue;   // skip center sample (same k for all p)
            const int w = k >> 5;             // compile-time after unroll
            #pragma unroll
            for (int p = 0; p < 4; p++)
                census_bit(a[p][w], v[p + j], c[p]);
            k++;
        }
    }
}

// block: 1024 flat (two 16-warp groups); grid: NBLOCKS (one wave)
__global__ __launch_bounds__(NTHREADS, 1)
void fused_census_loss(const float* __restrict__ left,
                       const float* __restrict__ right,
                       const float* __restrict__ disp,
                       float* __restrict__ out) {
    float*    lt  = smem_raw;                         // 12*512 f32
    float*    rt  = smem_raw + TILE_H * W;            // 12*512 f32
    unsigned* sc0 = (unsigned*)(smem_raw + 2 * TILE_H * W);
    unsigned* sc1 = sc0 + BH * WC;
    unsigned* sc2 = sc1 + BH * WC;

    __shared__ unsigned s_red[2];

    const int blk = blockIdx.x;
    const int b   = blk / ROWBLKS;
    const int h0  = (blk - b * ROWBLKS) * BH;

    const int tid = threadIdx.x;                 // 0..1023
    if (tid == 0) { s_red[0] = 0u; s_red[1] = 0u; }

    // two warp-aligned groups of 512 threads; 504 active quads per group
    const int  grp    = tid >> 9;                // 0: left(+gather), 1: right
    const int  qid    = tid & 511;               // 0..511
    const bool active = (qid < NQUADS);
    const int  rr     = qid / 126;               // 0..4 (clamped by 'active')
    const int  wx     = 4 * (qid - rr * 126);

    // early independent global load (grp0 only; consumed after the barrier)
    float4 dv = make_float4(0.f, 0.f, 0.f, 0.f);
    if (grp == 0 && active)
        dv = *(const float4*)&disp[((size_t)b * H + h0 + rr + 4) * W + wx + 4];

    // ---- Phase A: load both 12x512 tiles (rows h0..h0+11 always in range) ----
    {
        const float4* lg = (const float4*)(left  + (size_t)b * H * W + h0 * W);
        const float4* rg = (const float4*)(right + (size_t)b * H * W + h0 * W);
        float4* lt4 = (float4*)lt;
        float4* rt4 = (float4*)rt;
        #pragma unroll
        for (int i = tid; i < TILE_H * W / 4; i += NTHREADS) {
            lt4[i] = lg[i];
            rt4[i] = rg[i];
        }
    }
    __syncthreads();

    unsigned la[4][3];          // left census (grp0), carried across the barrier

    if (active) {
        if (grp == 0) {
            census4(lt, rr, wx, la);
        } else {
            unsigned a[4][3];
            census4(rt, rr, wx, a);
            const int o = rr * WC + wx;          // 16B-aligned
            *(uint4*)&sc0[o] = make_uint4(a[0][0], a[1][0], a[2][0], a[3][0]);
            *(uint4*)&sc1[o] = make_uint4(a[0][1], a[1][1], a[2][1], a[3][1]);
            *(uint4*)&sc2[o] = make_uint4(a[0][2], a[1][2], a[2][2], a[3][2]);
        }
    }

    __syncthreads();   // block-uniform: right-census stores visible

    unsigned cost = 0u, cnt = 0u;
    if (grp == 0 && active) {
        const float dd[4] = {dv.x, dv.y, dv.z, dv.w};
        #pragma unroll
        for (int p = 0; p < 4; p++) {
            if (dd[p] > 0.0f) {
                int ti = (int)dd[p];
                ti = ti < 0 ? 0 : (ti > MAX_DISP - 1 ? MAX_DISP - 1 : ti);
                const int widx = wx + p + ti;
                unsigned c;
                if (widx < WC) {
                    const int o = rr * WC + widx;
                    c = __popc(la[p][0] ^ sc0[o]) +
                        __popc(la[p][1] ^ sc1[o]) +
                        __popc(la[p][2] ^ sc2[o]);
                } else {
                    c = __popc(la[p][0]) + __popc(la[p][1]) + __popc(la[p][2]);
                }
                cost += c;
                cnt  += 1u;
            }
        }
    }

    // ---- Reduce: warp shfl -> smem atomics -> global ----
    #pragma unroll
    for (int off = 16; off > 0; off >>= 1) {
        cost += __shfl_down_sync(0xFFFFFFFFu, cost, off);
        cnt  += __shfl_down_sync(0xFFFFFFFFu, cnt,  off);
    }
    if ((tid & 31) == 0 && grp == 0) {
        atomicAdd(&s_red[0], cost);
        atomicAdd(&s_red[1], cnt);
    }
    __syncthreads();

    if (tid == 0) {
        atomicAdd(&g_acc[0], s_red[0]);
        atomicAdd(&g_acc[1], s_red[1]);
        __threadfence();
        const unsigned prev = atomicAdd(&g_done, 1u);
        if (prev == NBLOCKS - 1u) {
            const unsigned tc = atomicAdd(&g_acc[0], 0u);
            const unsigned tn = atomicAdd(&g_acc[1], 0u);
            out[0] = (float)tc / ((float)tn + 1e-6f);
            // reset for the next graph replay (visible at next kernel launch)
            g_acc[0] = 0u;
            g_acc[1] = 0u;
            g_done   = 0u;
        }
    }
}

#define SMEM_BYTES (2 * TILE_H * W * 4 + 3 * BH * WC * 4)   // 73344

extern "C" void kernel_launch(void* const* d_in, const int* in_sizes, int n_in,
                              void* d_out, int out_size) {
    const float* left  = (const float*)d_in[0];
    const float* right = (const float*)d_in[1];
    const float* disp  = (const float*)d_in[2];
    float* out = (float*)d_out;

    cudaFuncSetAttribute(fused_census_loss,
                         cudaFuncAttributeMaxDynamicSharedMemorySize, SMEM_BYTES);

    fused_census_loss<<<NBLOCKS, NTHREADS, SMEM_BYTES>>>(left, right, disp, out);
}

// round 9
// speedup vs baseline: 1.1910x; 1.1910x over previous
#include <cuda_runtime.h>
#include <cstdint>

#define RADIUS   4
#define MAX_DISP 192
#define BATCH    2
#define H        256
#define W        512
#define HC       248           // H - 8
#define WC       504           // W - 8
#define BH       4             // output rows per block
#define ROWBLKS  (HC / BH)     // 62
#define NBLOCKS  (ROWBLKS * BATCH)  // 124 -> one wave on 148 SMs
#define TILE_H   (BH + 2 * RADIUS)  // 12
#define NTHREADS 1024
#define NQUADS   (BH * (WC / 4))    // 504 quads per group

// integer-exact accumulators; module-load init = 0, last block resets after use
__device__ unsigned int g_acc[2] = {0u, 0u};
__device__ unsigned int g_done = 0u;

extern __shared__ float smem_raw[];
// layout: lt[12*512] f32 | rt[12*512] f32 | sc0..sc3[4*504] u32 each

// v > c  ->  1.0f else 0.0f : single SASS FSET.BF (no predicate).
__device__ __forceinline__ float fset_gt_f(float v, float c) {
    float r;
    asm("set.gt.f32.f32 %0, %1, %2;" : "=f"(r) : "f"(v), "f"(c));
    return r;
}

// Census for 4 consecutive pixels (row rr, cols wx..wx+3) from a 12x512 smem tile.
// 80 bits per pixel packed MSB-first into 4 words of 20 bits each, accumulated
// in fp32 (exact: values < 2^20 << 2^24) via FFMA-imm acc = acc*2 + bit.
// Bit order identical for left/right, which is all popc(XOR) needs.
__device__ __forceinline__ void census4(const float* __restrict__ t, int rr, int wx,
                                        unsigned a[4][4]) {
    const float4 cv = *(const float4*)&t[(rr + 4) * W + wx + 4];
    const float c[4] = {cv.x, cv.y, cv.z, cv.w};
    float f[4][4];
    #pragma unroll
    for (int p = 0; p < 4; p++)
        #pragma unroll
        for (int w = 0; w < 4; w++) f[p][w] = 0.0f;

    int k = 0;
    #pragma unroll
    for (int i = 0; i < 9; i++) {
        const float4 v0 = *(const float4*)&t[(rr + i) * W + wx];
        const float4 v1 = *(const float4*)&t[(rr + i) * W + wx + 4];
        const float4 v2 = *(const float4*)&t[(rr + i) * W + wx + 8];
        const float v[12] = {v0.x, v0.y, v0.z, v0.w,
                             v1.x, v1.y, v1.z, v1.w,
                             v2.x, v2.y, v2.z, v2.w};
        #pragma unroll
        for (int j = 0; j < 9; j++) {
            if (i == 4 && j == 4) continue;   // skip center (same k for all p)
            const int w = k / 20;             // compile-time after unroll
            #pragma unroll
            for (int p = 0; p < 4; p++) {
                const float bit = fset_gt_f(v[p + j], c[p]);   // ALU: FSET.BF
                f[p][w] = fmaf(f[p][w], 2.0f, bit);            // FMA: FFMA-imm
            }
            k++;
        }
    }
    #pragma unroll
    for (int p = 0; p < 4; p++)
        #pragma unroll
        for (int w = 0; w < 4; w++) a[p][w] = (unsigned)f[p][w];   // exact F2I
}

__device__ __forceinline__ void group_bar(int id) {
    asm volatile("bar.sync %0, %1;" :: "r"(id), "r"(512) : "memory");
}

// block: 1024 flat (two 16-warp groups); grid: NBLOCKS (one wave)
__global__ __launch_bounds__(NTHREADS, 1)
void fused_census_loss(const float* __restrict__ left,
                       const float* __restrict__ right,
                       const float* __restrict__ disp,
                       float* __restrict__ out) {
    float*    lt  = smem_raw;                         // 12*512 f32
    float*    rt  = smem_raw + TILE_H * W;            // 12*512 f32
    unsigned* sc0 = (unsigned*)(smem_raw + 2 * TILE_H * W);
    unsigned* sc1 = sc0 + BH * WC;
    unsigned* sc2 = sc1 + BH * WC;
    unsigned* sc3 = sc2 + BH * WC;

    __shared__ unsigned s_red[2];

    const int blk = blockIdx.x;
    const int b   = blk / ROWBLKS;
    const int h0  = (blk - b * ROWBLKS) * BH;

    const int tid = threadIdx.x;                 // 0..1023
    if (tid == 0) { s_red[0] = 0u; s_red[1] = 0u; }

    // two warp-aligned groups of 512; grp0: left(+gather), grp1: right
    const int  grp    = tid >> 9;
    const int  qid    = tid & 511;               // 0..511
    const bool active = (qid < NQUADS);
    const int  rr     = qid / 126;               // 0..4 (clamped by 'active')
    const int  wx     = 4 * (qid - rr * 126);

    // early independent global load (grp0 only; consumed after the full barrier)
    float4 dv = make_float4(0.f, 0.f, 0.f, 0.f);
    if (grp == 0 && active)
        dv = *(const float4*)&disp[((size_t)b * H + h0 + rr + 4) * W + wx + 4];

    // ---- Phase A: each group loads only its own 12x512 tile ----
    {
        const float* src = (grp == 0 ? left : right) + (size_t)b * H * W + h0 * W;
        float*       dst = (grp == 0 ? lt : rt);
        const float4* s4 = (const float4*)src;
        float4*       d4 = (float4*)dst;
        #pragma unroll
        for (int i = qid; i < TILE_H * W / 4; i += 512)
            d4[i] = s4[i];
    }
    // group-local barrier: grp0 waits only on lt, grp1 only on rt
    group_bar(1 + grp);

    unsigned la[4][4];          // left census (grp0), carried across the barrier

    if (active) {
        if (grp == 0) {
            census4(lt, rr, wx, la);
        } else {
            unsigned a[4][4];
            census4(rt, rr, wx, a);
            const int o = rr * WC + wx;          // 16B-aligned
            *(uint4*)&sc0[o] = make_uint4(a[0][0], a[1][0], a[2][0], a[3][0]);
            *(uint4*)&sc1[o] = make_uint4(a[0][1], a[1][1], a[2][1], a[3][1]);
            *(uint4*)&sc2[o] = make_uint4(a[0][2], a[1][2], a[2][2], a[3][2]);
            *(uint4*)&sc3[o] = make_uint4(a[0][3], a[1][3], a[2][3], a[3][3]);
        }
    }

    __syncthreads();   // block-uniform: right-census stores visible to grp0

    unsigned cost = 0u, cnt = 0u;
    if (grp == 0 && active) {
        const float dd[4] = {dv.x, dv.y, dv.z, dv.w};
        #pragma unroll
        for (int p = 0; p < 4; p++) {
            if (dd[p] > 0.0f) {
                int ti = (int)dd[p];
                ti = ti < 0 ? 0 : (ti > MAX_DISP - 1 ? MAX_DISP - 1 : ti);
                const int widx = wx + p + ti;
                unsigned c;
                if (widx < WC) {
                    const int o = rr * WC + widx;
                    c = __popc(la[p][0] ^ sc0[o]) +
                        __popc(la[p][1] ^ sc1[o]) +
                        __popc(la[p][2] ^ sc2[o]) +
                        __popc(la[p][3] ^ sc3[o]);
                } else {
                    c = __popc(la[p][0]) + __popc(la[p][1]) +
                        __popc(la[p][2]) + __popc(la[p][3]);
                }
                cost += c;
                cnt  += 1u;
            }
        }
    }

    // ---- Reduce: warp shfl -> smem atomics -> global ----
    #pragma unroll
    for (int off = 16; off > 0; off >>= 1) {
        cost += __shfl_down_sync(0xFFFFFFFFu, cost, off);
        cnt  += __shfl_down_sync(0xFFFFFFFFu, cnt,  off);
    }
    if ((tid & 31) == 0 && grp == 0) {
        atomicAdd(&s_red[0], cost);
        atomicAdd(&s_red[1], cnt);
    }
    __syncthreads();

    if (tid == 0) {
        atomicAdd(&g_acc[0], s_red[0]);
        atomicAdd(&g_acc[1], s_red[1]);
        __threadfence();
        const unsigned prev = atomicAdd(&g_done, 1u);
        if (prev == NBLOCKS - 1u) {
            const unsigned tc = atomicAdd(&g_acc[0], 0u);
            const unsigned tn = atomicAdd(&g_acc[1], 0u);
            out[0] = (float)tc / ((float)tn + 1e-6f);
            // reset for the next graph replay (visible at next kernel launch)
            g_acc[0] = 0u;
            g_acc[1] = 0u;
            g_done   = 0u;
        }
    }
}

#define SMEM_BYTES (2 * TILE_H * W * 4 + 4 * BH * WC * 4)   // 81408

extern "C" void kernel_launch(void* const* d_in, const int* in_sizes, int n_in,
                              void* d_out, int out_size) {
    const float* left  = (const float*)d_in[0];
    const float* right = (const float*)d_in[1];
    const float* disp  = (const float*)d_in[2];
    float* out = (float*)d_out;

    cudaFuncSetAttribute(fused_census_loss,
                         cudaFuncAttributeMaxDynamicSharedMemorySize, SMEM_BYTES);

    fused_census_loss<<<NBLOCKS, NTHREADS, SMEM_BYTES>>>(left, right, disp, out);
}